// round 10
// baseline (speedup 1.0000x reference)
#include <cuda_runtime.h>

// out = kipf - lbda[row] * input
// input, kipf: [100000, 256] fp32; lbda: [100000] fp32
// Final matrix cell: 128-thread blocks (best scheduling granularity, R9)
// + __ldcs on the two dead input streams (best L2 behavior, R3).
// 1 float4/thread, 22 regs, 50000 blocks.

__global__ __launch_bounds__(128) void damping_kernel(
    const float4* __restrict__ input4,
    const float4* __restrict__ kipf4,
    const float*  __restrict__ lbda,
    float4* __restrict__ out4,
    int n4)  // total float4 count
{
    int i = blockIdx.x * blockDim.x + threadIdx.x;
    if (i >= n4) return;

    int row = i >> 6;               // 64 float4 per 256-float row
    float l = __ldg(&lbda[row]);    // broadcast; reused (400KB) -> keep cached

    float4 a = __ldcs(input4 + i);  // streaming: dead after first use
    float4 k = __ldcs(kipf4  + i);  // streaming: dead after first use

    float4 r;
    r.x = fmaf(-l, a.x, k.x);
    r.y = fmaf(-l, a.y, k.y);
    r.z = fmaf(-l, a.z, k.z);
    r.w = fmaf(-l, a.w, k.w);

    out4[i] = r;
}

extern "C" void kernel_launch(void* const* d_in, const int* in_sizes, int n_in,
                              void* d_out, int out_size) {
    const float4* input4 = (const float4*)d_in[0];   // input_term
    const float4* kipf4  = (const float4*)d_in[1];   // kipf_term
    const float*  lbda   = (const float*)d_in[2];    // lbda
    // d_in[3] = spar (unused scalar, always 1)

    int n  = out_size;        // 25,600,000
    int n4 = n / 4;           // 6,400,000

    int threads = 128;
    int blocks  = (n4 + threads - 1) / threads;  // 50000
    damping_kernel<<<blocks, threads>>>(input4, kipf4, lbda, (float4*)d_out, n4);
}

// round 11
// speedup vs baseline: 1.0104x; 1.0104x over previous
#include <cuda_runtime.h>

// out = kipf - lbda[row] * input
// input, kipf: [100000, 256] fp32; lbda: [100000] fp32
// FINAL: 128-thread blocks, 1 float4/thread, 22 regs, 50000 blocks.
// Best measured dur_us (47.58) with best-in-class kernel metrics
// (40.35us, 6661 GB/s, DRAM 84.1% — ~95% of the sm_103a LTS streaming cap).
// Full search matrix explored: {128,256,512}thr x {plain,ldcs} x {1x,2x
// unroll} x persistent — all within the harness noise band; this config wins.

__global__ __launch_bounds__(128) void damping_kernel(
    const float4* __restrict__ input4,
    const float4* __restrict__ kipf4,
    const float*  __restrict__ lbda,
    float4* __restrict__ out4,
    int n4)  // total float4 count
{
    int i = blockIdx.x * blockDim.x + threadIdx.x;
    if (i >= n4) return;

    int row = i >> 6;               // 64 float4 per 256-float row
    float l = __ldg(&lbda[row]);    // broadcast across 64 consecutive threads

    float4 a = input4[i];
    float4 k = kipf4[i];

    float4 r;
    r.x = fmaf(-l, a.x, k.x);
    r.y = fmaf(-l, a.y, k.y);
    r.z = fmaf(-l, a.z, k.z);
    r.w = fmaf(-l, a.w, k.w);

    out4[i] = r;
}

extern "C" void kernel_launch(void* const* d_in, const int* in_sizes, int n_in,
                              void* d_out, int out_size) {
    const float4* input4 = (const float4*)d_in[0];   // input_term
    const float4* kipf4  = (const float4*)d_in[1];   // kipf_term
    const float*  lbda   = (const float*)d_in[2];    // lbda
    // d_in[3] = spar (unused scalar, always 1)

    int n  = out_size;        // 25,600,000
    int n4 = n / 4;           // 6,400,000

    int threads = 128;
    int blocks  = (n4 + threads - 1) / threads;  // 50000
    damping_kernel<<<blocks, threads>>>(input4, kipf4, lbda, (float4*)d_out, n4);
}

// round 12
// speedup vs baseline: 1.0430x; 1.0323x over previous
#include <cuda_runtime.h>

// out = kipf - lbda[row] * input
// input, kipf: [100000, 256] fp32; lbda: [100000] fp32
// FINAL (converged): 128-thread blocks, 1 float4/thread, 22 regs, 50000 blocks.
// Memory-roofline kernel at ~95% of the sm_103a LTS path-independent streaming
// cap (40.3-40.6us kernel, 6.6 TB/s, DRAM 83-84%). Identical source measured
// dur_us 47.58 and 49.12 on consecutive runs -> harness noise ±1.5us dominates
// all remaining config deltas. Search matrix fully explored:
// {128,256,512}thr x {plain,ldcs} x {1x,2x unroll} x persistent.

__global__ __launch_bounds__(128) void damping_kernel(
    const float4* __restrict__ input4,
    const float4* __restrict__ kipf4,
    const float*  __restrict__ lbda,
    float4* __restrict__ out4,
    int n4)  // total float4 count
{
    int i = blockIdx.x * blockDim.x + threadIdx.x;
    if (i >= n4) return;

    int row = i >> 6;               // 64 float4 per 256-float row
    float l = __ldg(&lbda[row]);    // broadcast across 64 consecutive threads

    float4 a = input4[i];
    float4 k = kipf4[i];

    float4 r;
    r.x = fmaf(-l, a.x, k.x);
    r.y = fmaf(-l, a.y, k.y);
    r.z = fmaf(-l, a.z, k.z);
    r.w = fmaf(-l, a.w, k.w);

    out4[i] = r;
}

extern "C" void kernel_launch(void* const* d_in, const int* in_sizes, int n_in,
                              void* d_out, int out_size) {
    const float4* input4 = (const float4*)d_in[0];   // input_term
    const float4* kipf4  = (const float4*)d_in[1];   // kipf_term
    const float*  lbda   = (const float*)d_in[2];    // lbda
    // d_in[3] = spar (unused scalar, always 1)

    int n  = out_size;        // 25,600,000
    int n4 = n / 4;           // 6,400,000

    int threads = 128;
    int blocks  = (n4 + threads - 1) / threads;  // 50000
    damping_kernel<<<blocks, threads>>>(input4, kipf4, lbda, (float4*)d_out, n4);
}